// round 13
// baseline (speedup 1.0000x reference)
#include <cuda_runtime.h>
#include <cuda_bf16.h>
#include <cstdint>

// GMM: out[m] = sum_n w[n]*coef*exp(-(|x|^2+|mu|^2-2 x.mu)/2)
// R13: bf16 k16 GEMM, 512 threads/CTA (16 warps, 4/SMSP) to fix the
// latency/occupancy bound R12's profile exposed (tensor=46.9%, occ=12.5%).
// Warp grid 4m x 4n, warp tile 32x32. Regs held ~<=120: A-frags preloaded for
// 6/8 k-slices, acc[32], no cross-chunk staging. Order MMA->epi->sync->refill
// (also removes R6's bw-overwrite race).

#define M_DIM 16384
#define N_DIM 8192
#define NCHUNK 64
#define NSTAGE 4
#define COEF 0.15915494309189535f          // 1/(2*pi)
#define LOG2E_F 1.4426950408889634f
#define NHL (-0.72134752044448170368f)     // -0.5*log2(e)

// Pre-swizzled bf16 panels: [block][128 rows][256B], 32KB/block.
// Within a row, 16B-chunk c sits at byte col (c*16) ^ ((row&7)<<4).
__device__ __align__(128) char g_x[(M_DIM / 128) * 32768];   // 4 MB
__device__ __align__(128) char g_m[(N_DIM / 128) * 32768];   // 2 MB
__device__ float g_ax[M_DIM];                // -0.5*log2e*|x_m|^2
__device__ __align__(16) float2 g_bw[N_DIM]; // (-0.5*log2e*|mu_n|^2, w_n*coef)

// ---------------- smem layout (bytes) ----------------
#define MB_S   0                             // 4 stage mbarriers (8B each)
#define MB_X   32
#define OFF_BW 64                            // 4 slots x 1024B
#define OFF_X  5120                          // x panel 32KB
#define OFF_M  38912                         // 4 stage bufs x 32KB
#define SMEM_BYTES (OFF_M + NSTAGE * 32768)  // 169984

// ---------------- helpers ----------------
__device__ __forceinline__ uint32_t smem_u32(const void* p) {
    uint32_t a;
    asm("{ .reg .u64 t; cvta.to.shared.u64 t, %1; cvt.u32.u64 %0, t; }" : "=r"(a) : "l"(p));
    return a;
}
__device__ __forceinline__ void mbar_init(uint32_t addr, uint32_t cnt) {
    asm volatile("mbarrier.init.shared.b64 [%0], %1;" :: "r"(addr), "r"(cnt) : "memory");
}
__device__ __forceinline__ void mbar_expect(uint32_t addr, uint32_t bytes) {
    asm volatile("mbarrier.arrive.expect_tx.shared.b64 _, [%0], %1;"
                 :: "r"(addr), "r"(bytes) : "memory");
}
__device__ __forceinline__ void mbar_wait(uint32_t addr, uint32_t parity) {
    asm volatile(
        "{\n\t.reg .pred P;\n"
        "WL_%=:\n\t"
        "mbarrier.try_wait.parity.shared.b64 P, [%0], %1;\n\t"
        "@!P bra WL_%=;\n\t}"
        :: "r"(addr), "r"(parity) : "memory");
}
__device__ __forceinline__ void bulk_g2s(uint32_t dst, const void* src,
                                         uint32_t bytes, uint32_t mbar) {
    asm volatile(
        "cp.async.bulk.shared::cluster.global.mbarrier::complete_tx::bytes "
        "[%0], [%1], %2, [%3];"
        :: "r"(dst), "l"(src), "r"(bytes), "r"(mbar) : "memory");
}
__device__ __forceinline__ void ldsm4(uint32_t& r0, uint32_t& r1, uint32_t& r2,
                                      uint32_t& r3, uint32_t addr) {
    asm volatile("ldmatrix.sync.aligned.m8n8.x4.shared.b16 {%0,%1,%2,%3}, [%4];"
                 : "=r"(r0), "=r"(r1), "=r"(r2), "=r"(r3) : "r"(addr));
}
__device__ __forceinline__ void mma16816(float& c0, float& c1, float& c2, float& c3,
                                         uint32_t a0, uint32_t a1, uint32_t a2, uint32_t a3,
                                         uint32_t b0, uint32_t b1) {
    asm volatile(
        "mma.sync.aligned.m16n8k16.row.col.f32.bf16.bf16.f32 "
        "{%0,%1,%2,%3}, {%4,%5,%6,%7}, {%8,%9}, {%0,%1,%2,%3};"
        : "+f"(c0), "+f"(c1), "+f"(c2), "+f"(c3)
        : "r"(a0), "r"(a1), "r"(a2), "r"(a3), "r"(b0), "r"(b1));
}
__device__ __forceinline__ void mma16816_z(float& c0, float& c1, float& c2, float& c3,
                                           uint32_t a0, uint32_t a1, uint32_t a2, uint32_t a3,
                                           uint32_t b0, uint32_t b1) {
    asm volatile(
        "mma.sync.aligned.m16n8k16.row.col.f32.bf16.bf16.f32 "
        "{%0,%1,%2,%3}, {%4,%5,%6,%7}, {%8,%9}, {%10,%10,%10,%10};"
        : "=f"(c0), "=f"(c1), "=f"(c2), "=f"(c3)
        : "r"(a0), "r"(a1), "r"(a2), "r"(a3), "r"(b0), "r"(b1), "f"(0.f));
}
// e = 2^arg if arg > -126 else 0 (matches ex2.approx.ftz flush-to-zero)
__device__ __forceinline__ float ex2_pred(float arg) {
    float e = 0.f;
    asm("{\n\t.reg .pred p;\n\t"
        "setp.gt.f32 p, %1, 0fC2FC0000;\n\t"
        "@p ex2.approx.ftz.f32 %0, %1;\n\t}"
        : "+f"(e) : "f"(arg));
    return e;
}
__device__ __forceinline__ uint32_t pkbf(__nv_bfloat16 a, __nv_bfloat16 b) {
    __nv_bfloat162 t(a, b);
    return *reinterpret_cast<uint32_t*>(&t);
}

// ---------------- merged prologue: fp32 -> bf16 (pre-swizzled), norms --------
__global__ void prep(const float* __restrict__ x, const float* __restrict__ means,
                     const float* __restrict__ w) {
    int gr = blockIdx.x * 8 + (threadIdx.x >> 5);
    int lane = threadIdx.x & 31;
    const bool is_x = gr < M_DIM;
    int row = is_x ? gr : gr - M_DIM;
    const float* src = (is_x ? x : means) + (size_t)row * 128;
    char* dstb = (is_x ? g_x : g_m) + (size_t)(row >> 7) * 32768;
    int r = row & 127;

    float4 v = reinterpret_cast<const float4*>(src)[lane];
    float s = v.x * v.x + v.y * v.y + v.z * v.z + v.w * v.w;
    uint2 hv = make_uint2(pkbf(__float2bfloat16_rn(v.x), __float2bfloat16_rn(v.y)),
                          pkbf(__float2bfloat16_rn(v.z), __float2bfloat16_rn(v.w)));
    uint32_t off = (uint32_t)r * 256
                 + (((uint32_t)(lane >> 1) * 16) ^ (((uint32_t)r & 7) << 4))
                 + (uint32_t)(lane & 1) * 8;
    *reinterpret_cast<uint2*>(dstb + off) = hv;
#pragma unroll
    for (int o = 16; o; o >>= 1) s += __shfl_down_sync(0xffffffffu, s, o);
    if (lane == 0) {
        if (is_x) g_ax[row] = NHL * s;
        else      g_bw[row] = make_float2(NHL * s, w[row] * COEF);
    }
}

// ---------------- main fused kernel ----------------
// 128 CTAs x 512 threads (16 warps, 4/SMSP). Warp grid 4m x 4n, tile 32x32.
// Per chunk per warp: 8 ks x 2 mt x 4 np = 64 MMAs.
__global__ __launch_bounds__(512, 1) void gmm_mma(float* __restrict__ out) {
    extern __shared__ char smem[];
    const uint32_t sb = smem_u32(smem);
    const int tid = threadIdx.x, wid = tid >> 5, lane = tid & 31;
    const int wm = wid >> 2, wn = wid & 3;
    const int m0 = blockIdx.x * 128;

    if (tid == 0) {
#pragma unroll
        for (int s = 0; s < NSTAGE; s++) mbar_init(sb + MB_S + s * 8, 1);
        mbar_init(sb + MB_X, 1);
    }
    __syncthreads();
    if (tid == 0) {
        mbar_expect(sb + MB_X, 32768);
        bulk_g2s(sb + OFF_X, g_x + (size_t)blockIdx.x * 32768, 32768, sb + MB_X);
#pragma unroll
        for (int s = 0; s < NSTAGE; s++) {
            mbar_expect(sb + MB_S + s * 8, 33792);
            bulk_g2s(sb + OFF_M + s * 32768, g_m + (size_t)s * 32768, 32768, sb + MB_S + s * 8);
            bulk_g2s(sb + OFF_BW + s * 1024, (const char*)g_bw + (size_t)s * 1024, 1024,
                     sb + MB_S + s * 8);
        }
    }

    float axv[4];
#pragma unroll
    for (int mt = 0; mt < 2; mt++)
#pragma unroll
        for (int h = 0; h < 2; h++)
            axv[mt * 2 + h] = g_ax[m0 + wm * 32 + mt * 16 + h * 8 + (lane >> 2)];

    float s[4] = {0.f, 0.f, 0.f, 0.f};

    const uint32_t sx = (uint32_t)((lane & 7) << 4);
    const uint32_t h16 = (uint32_t)((lane >> 4) * 16);
    const uint32_t aLin = sb + OFF_X + (uint32_t)((wm * 32 + (lane & 15)) * 256);
    const uint32_t bLin = (uint32_t)((wn * 32 + (lane & 15)) * 256);
    const int bwIdx = wn * 16 + (lane & 3);

    mbar_wait(sb + MB_X, 0);

    // Preload A fragments for k-slices 0..5 (48 regs); ks 6,7 via LDSM in-loop.
    uint32_t ah[6][2][4];
#pragma unroll
    for (int ks = 0; ks < 6; ks++) {
        const uint32_t ko = ((uint32_t)(ks * 32) + h16) ^ sx;
#pragma unroll
        for (int mt = 0; mt < 2; mt++)
            ldsm4(ah[ks][mt][0], ah[ks][mt][1], ah[ks][mt][2], ah[ks][mt][3],
                  aLin + (uint32_t)(mt * 4096) + ko);
    }

    for (int i = 0; i < NCHUNK; i++) {
        const int st = i & (NSTAGE - 1);
        mbar_wait(sb + MB_S + st * 8, (uint32_t)(i >> 2) & 1);

        float acc[32];
        const uint32_t pb = sb + OFF_M + st * 32768 + bLin;
#pragma unroll
        for (int ks = 0; ks < 8; ks++) {
            const uint32_t ko = ((uint32_t)(ks * 32) + h16) ^ sx;
            uint32_t at[2][4];
            if (ks >= 6) {
#pragma unroll
                for (int mt = 0; mt < 2; mt++)
                    ldsm4(at[mt][0], at[mt][1], at[mt][2], at[mt][3],
                          aLin + (uint32_t)(mt * 4096) + ko);
            } else {
#pragma unroll
                for (int mt = 0; mt < 2; mt++)
#pragma unroll
                    for (int q = 0; q < 4; q++) at[mt][q] = ah[ks][mt][q];
            }
            uint32_t bf[2][4];   // group g covers n-tiles 2g, 2g+1
#pragma unroll
            for (int g = 0; g < 2; g++)
                ldsm4(bf[g][0], bf[g][1], bf[g][2], bf[g][3],
                      pb + (uint32_t)(g * 4096) + ko);
#pragma unroll
            for (int mt = 0; mt < 2; mt++)
#pragma unroll
                for (int g = 0; g < 2; g++) {
                    float* c0 = &acc[(mt * 4 + g * 2) * 4];
                    float* c1 = &acc[(mt * 4 + g * 2 + 1) * 4];
                    if (ks == 0) {
                        mma16816_z(c0[0], c0[1], c0[2], c0[3],
                                   at[mt][0], at[mt][1], at[mt][2], at[mt][3],
                                   bf[g][0], bf[g][2]);
                        mma16816_z(c1[0], c1[1], c1[2], c1[3],
                                   at[mt][0], at[mt][1], at[mt][2], at[mt][3],
                                   bf[g][1], bf[g][3]);
                    } else {
                        mma16816(c0[0], c0[1], c0[2], c0[3],
                                 at[mt][0], at[mt][1], at[mt][2], at[mt][3],
                                 bf[g][0], bf[g][2]);
                        mma16816(c1[0], c1[1], c1[2], c1[3],
                                 at[mt][0], at[mt][1], at[mt][2], at[mt][3],
                                 bf[g][1], bf[g][3]);
                    }
                }
        }

        // fused epilogue (before sync: bw slot st is still valid)
        const float4* bwp = reinterpret_cast<const float4*>(smem + OFF_BW + st * 1024);
#pragma unroll
        for (int nt = 0; nt < 4; nt++) {
            float4 bw4 = bwp[bwIdx + nt * 4];
#pragma unroll
            for (int mt = 0; mt < 2; mt++)
#pragma unroll
                for (int h = 0; h < 2; h++) {
                    float d0 = acc[(mt * 4 + nt) * 4 + h * 2];
                    float d1 = acc[(mt * 4 + nt) * 4 + h * 2 + 1];
                    float base = axv[mt * 2 + h];
                    float e0 = ex2_pred(fmaf(LOG2E_F, d0, base + bw4.x));
                    float e1 = ex2_pred(fmaf(LOG2E_F, d1, base + bw4.z));
                    s[mt * 2 + h] = fmaf(bw4.y, e0, s[mt * 2 + h]);
                    s[mt * 2 + h] = fmaf(bw4.w, e1, s[mt * 2 + h]);
                }
        }

        __syncthreads();   // all warps done with stage st (tiles + bw)
        if (tid == 0 && i + NSTAGE < NCHUNK) {
            const int c = i + NSTAGE;
            const uint32_t mb = sb + MB_S + st * 8;
            mbar_expect(mb, 33792);
            bulk_g2s(sb + OFF_M + st * 32768, g_m + (size_t)c * 32768, 32768, mb);
            bulk_g2s(sb + OFF_BW + st * 1024, (const char*)g_bw + (size_t)c * 1024, 1024, mb);
        }
    }

    // reduce: quad lanes (cols) -> smem (4 n-warps) -> out
#pragma unroll
    for (int k = 0; k < 4; k++) {
        s[k] += __shfl_xor_sync(0xffffffffu, s[k], 1);
        s[k] += __shfl_xor_sync(0xffffffffu, s[k], 2);
    }
    float* red = reinterpret_cast<float*>(smem + OFF_X);
    __syncthreads();
    if ((lane & 3) == 0) {
#pragma unroll
        for (int mt = 0; mt < 2; mt++)
#pragma unroll
            for (int h = 0; h < 2; h++) {
                int row = wm * 32 + mt * 16 + h * 8 + (lane >> 2);
                red[row * 4 + wn] = s[mt * 2 + h];
            }
    }
    __syncthreads();
    if (tid < 128)
        out[m0 + tid] = (red[tid * 4] + red[tid * 4 + 1])
                      + (red[tid * 4 + 2] + red[tid * 4 + 3]);
}

// ---------------------------------------------------------------------------
extern "C" void kernel_launch(void* const* d_in, const int* in_sizes, int n_in,
                              void* d_out, int out_size) {
    const float* x = (const float*)d_in[0];      // [16384, 128]
    const float* means = (const float*)d_in[1];  // [8192, 128]
    const float* w = (const float*)d_in[2];      // [8192]
    float* out = (float*)d_out;                  // [16384]
    (void)in_sizes; (void)n_in; (void)out_size;

    cudaFuncSetAttribute(gmm_mma, cudaFuncAttributeMaxDynamicSharedMemorySize, SMEM_BYTES);

    prep<<<(M_DIM + N_DIM) / 8, 256>>>(x, means, w);
    gmm_mma<<<128, 512, SMEM_BYTES>>>(out);
}

// round 14
// speedup vs baseline: 1.1438x; 1.1438x over previous
#include <cuda_runtime.h>
#include <cuda_bf16.h>
#include <cstdint>

// GMM: out[m] = sum_n w[n]*coef*exp(-(|x|^2+|mu|^2-2 x.mu)/2)
// R14: bf16 k16 mma.sync at its measured per-SMSP floor -> the lever left is
// chip-level: balanced persistent decomposition over 148 CTAs (vs 128 = 13.5%
// idle SMs). Each CTA runs a contiguous slice of the 8192 (mtile,chunk) tasks
// (<=2 mtiles), means-pipeline never drains across the boundary; <=2 partial
// vectors per CTA; tiny deterministic reduce recombines. 256 thr, 4m x 2n.

#define M_DIM 16384
#define N_DIM 8192
#define NCTA 148
#define NTASK 8192                          // 128 mtiles x 64 chunks
#define NSTAGE 4
#define COEF 0.15915494309189535f           // 1/(2*pi)
#define LOG2E_F 1.4426950408889634f
#define NHL (-0.72134752044448170368f)      // -0.5*log2(e)

// Pre-swizzled bf16 panels: [block][128 rows][256B], 32KB/block.
__device__ __align__(128) char g_x[(M_DIM / 128) * 32768];   // 4 MB
__device__ __align__(128) char g_m[(N_DIM / 128) * 32768];   // 2 MB
__device__ float g_ax[M_DIM];                // -0.5*log2e*|x_m|^2
__device__ __align__(16) float2 g_bw[N_DIM]; // (-0.5*log2e*|mu_n|^2, w_n*coef)
__device__ float g_part[NCTA * 2 * 128];     // per-CTA per-segment partials

// ---------------- smem layout (bytes) ----------------
#define MB_S    0                            // 4 stage mbarriers
#define MB_X    32
#define OFF_BW  64                           // 4 slots x 1024B -> ends 4160
#define OFF_RED 4224                         // 1KB reduce scratch
#define OFF_X   5376                         // x panel 32KB
#define OFF_M   38144                        // 4 stage bufs x 32KB
#define SMEM_BYTES (OFF_M + NSTAGE * 32768)  // 169216

// ---------------- helpers ----------------
__device__ __forceinline__ uint32_t smem_u32(const void* p) {
    uint32_t a;
    asm("{ .reg .u64 t; cvta.to.shared.u64 t, %1; cvt.u32.u64 %0, t; }" : "=r"(a) : "l"(p));
    return a;
}
__device__ __forceinline__ void mbar_init(uint32_t addr, uint32_t cnt) {
    asm volatile("mbarrier.init.shared.b64 [%0], %1;" :: "r"(addr), "r"(cnt) : "memory");
}
__device__ __forceinline__ void mbar_expect(uint32_t addr, uint32_t bytes) {
    asm volatile("mbarrier.arrive.expect_tx.shared.b64 _, [%0], %1;"
                 :: "r"(addr), "r"(bytes) : "memory");
}
__device__ __forceinline__ void mbar_wait(uint32_t addr, uint32_t parity) {
    asm volatile(
        "{\n\t.reg .pred P;\n"
        "WL_%=:\n\t"
        "mbarrier.try_wait.parity.shared.b64 P, [%0], %1;\n\t"
        "@!P bra WL_%=;\n\t}"
        :: "r"(addr), "r"(parity) : "memory");
}
__device__ __forceinline__ void bulk_g2s(uint32_t dst, const void* src,
                                         uint32_t bytes, uint32_t mbar) {
    asm volatile(
        "cp.async.bulk.shared::cluster.global.mbarrier::complete_tx::bytes "
        "[%0], [%1], %2, [%3];"
        :: "r"(dst), "l"(src), "r"(bytes), "r"(mbar) : "memory");
}
__device__ __forceinline__ void ldsm4(uint32_t& r0, uint32_t& r1, uint32_t& r2,
                                      uint32_t& r3, uint32_t addr) {
    asm volatile("ldmatrix.sync.aligned.m8n8.x4.shared.b16 {%0,%1,%2,%3}, [%4];"
                 : "=r"(r0), "=r"(r1), "=r"(r2), "=r"(r3) : "r"(addr));
}
__device__ __forceinline__ void mma16816(float& c0, float& c1, float& c2, float& c3,
                                         uint32_t a0, uint32_t a1, uint32_t a2, uint32_t a3,
                                         uint32_t b0, uint32_t b1) {
    asm volatile(
        "mma.sync.aligned.m16n8k16.row.col.f32.bf16.bf16.f32 "
        "{%0,%1,%2,%3}, {%4,%5,%6,%7}, {%8,%9}, {%0,%1,%2,%3};"
        : "+f"(c0), "+f"(c1), "+f"(c2), "+f"(c3)
        : "r"(a0), "r"(a1), "r"(a2), "r"(a3), "r"(b0), "r"(b1));
}
__device__ __forceinline__ void mma16816_z(float& c0, float& c1, float& c2, float& c3,
                                           uint32_t a0, uint32_t a1, uint32_t a2, uint32_t a3,
                                           uint32_t b0, uint32_t b1) {
    asm volatile(
        "mma.sync.aligned.m16n8k16.row.col.f32.bf16.bf16.f32 "
        "{%0,%1,%2,%3}, {%4,%5,%6,%7}, {%8,%9}, {%10,%10,%10,%10};"
        : "=f"(c0), "=f"(c1), "=f"(c2), "=f"(c3)
        : "r"(a0), "r"(a1), "r"(a2), "r"(a3), "r"(b0), "r"(b1), "f"(0.f));
}
__device__ __forceinline__ float ex2_pred(float arg) {
    float e = 0.f;
    asm("{\n\t.reg .pred p;\n\t"
        "setp.gt.f32 p, %1, 0fC2FC0000;\n\t"
        "@p ex2.approx.ftz.f32 %0, %1;\n\t}"
        : "+f"(e) : "f"(arg));
    return e;
}
__device__ __forceinline__ uint32_t pkbf(__nv_bfloat16 a, __nv_bfloat16 b) {
    __nv_bfloat162 t(a, b);
    return *reinterpret_cast<uint32_t*>(&t);
}

// ---------------- merged prologue: fp32 -> bf16 (pre-swizzled), norms --------
__global__ void prep(const float* __restrict__ x, const float* __restrict__ means,
                     const float* __restrict__ w) {
    int gr = blockIdx.x * 8 + (threadIdx.x >> 5);
    int lane = threadIdx.x & 31;
    const bool is_x = gr < M_DIM;
    int row = is_x ? gr : gr - M_DIM;
    const float* src = (is_x ? x : means) + (size_t)row * 128;
    char* dstb = (is_x ? g_x : g_m) + (size_t)(row >> 7) * 32768;
    int r = row & 127;

    float4 v = reinterpret_cast<const float4*>(src)[lane];
    float s = v.x * v.x + v.y * v.y + v.z * v.z + v.w * v.w;
    uint2 hv = make_uint2(pkbf(__float2bfloat16_rn(v.x), __float2bfloat16_rn(v.y)),
                          pkbf(__float2bfloat16_rn(v.z), __float2bfloat16_rn(v.w)));
    uint32_t off = (uint32_t)r * 256
                 + (((uint32_t)(lane >> 1) * 16) ^ (((uint32_t)r & 7) << 4))
                 + (uint32_t)(lane & 1) * 8;
    *reinterpret_cast<uint2*>(dstb + off) = hv;
#pragma unroll
    for (int o = 16; o; o >>= 1) s += __shfl_down_sync(0xffffffffu, s, o);
    if (lane == 0) {
        if (is_x) g_ax[row] = NHL * s;
        else      g_bw[row] = make_float2(NHL * s, w[row] * COEF);
    }
}

// ---------------- main fused kernel (persistent, balanced) ----------------
// 148 CTAs x 256 threads. Warp grid 4m x 2n, warp tile 32m x 64n.
__global__ __launch_bounds__(256, 1) void gmm_mma() {
    extern __shared__ char smem[];
    const uint32_t sb = smem_u32(smem);
    const int tid = threadIdx.x, wid = tid >> 5, lane = tid & 31;
    const int wm = wid >> 1, wn = wid & 1;

    const int cta = blockIdx.x;
    const uint32_t t0 = (uint32_t)(cta * NTASK) / NCTA;
    const uint32_t t1 = (uint32_t)((cta + 1) * NTASK) / NCTA;
    const int J = (int)(t1 - t0);
    const int mt0 = (int)(t0 >> 6), mt1 = (int)((t1 - 1) >> 6);
    const int c0 = (int)(t0 & 63);
    const bool twoseg = (mt1 > mt0);
    const int len0 = twoseg ? (64 - c0) : J;
#define CHUNK(j) ((j) < len0 ? c0 + (j) : (j) - len0)

    if (tid == 0) {
#pragma unroll
        for (int s = 0; s < NSTAGE; s++) mbar_init(sb + MB_S + s * 8, 1);
        mbar_init(sb + MB_X, 1);
    }
    __syncthreads();
    if (tid == 0) {
        mbar_expect(sb + MB_X, 32768);
        bulk_g2s(sb + OFF_X, g_x + (size_t)mt0 * 32768, 32768, sb + MB_X);
#pragma unroll
        for (int s = 0; s < NSTAGE; s++) {
            const int cn = CHUNK(s);
            mbar_expect(sb + MB_S + s * 8, 33792);
            bulk_g2s(sb + OFF_M + s * 32768, g_m + (size_t)cn * 32768, 32768, sb + MB_S + s * 8);
            bulk_g2s(sb + OFF_BW + s * 1024, (const char*)g_bw + (size_t)cn * 1024, 1024,
                     sb + MB_S + s * 8);
        }
    }

    const uint32_t sx = (uint32_t)((lane & 7) << 4);
    const uint32_t h16 = (uint32_t)((lane >> 4) * 16);
    const uint32_t aLin = sb + OFF_X + (uint32_t)((wm * 32 + (lane & 15)) * 256);
    const uint32_t bLin = (uint32_t)((wn * 64 + (lane & 15)) * 256);
    const int bwIdx = wn * 32 + (lane & 3);
    float* red = reinterpret_cast<float*>(smem + OFF_RED);

    float axv[4], s[4] = {0.f, 0.f, 0.f, 0.f};
    uint32_t ah[8][2][4];
    uint32_t phmask = 0, xph = 0;

#define LOAD_AX(MT)                                                           \
    {                                                                         \
        _Pragma("unroll")                                                     \
        for (int mtl = 0; mtl < 2; mtl++)                                     \
            _Pragma("unroll")                                                 \
            for (int h = 0; h < 2; h++)                                       \
                axv[mtl * 2 + h] =                                            \
                    g_ax[(MT) * 128 + wm * 32 + mtl * 16 + h * 8 + (lane >> 2)]; \
    }
#define LOAD_A()                                                              \
    {                                                                         \
        _Pragma("unroll")                                                     \
        for (int ks = 0; ks < 8; ks++) {                                      \
            const uint32_t ko = ((uint32_t)(ks * 32) + h16) ^ sx;             \
            _Pragma("unroll")                                                 \
            for (int mtl = 0; mtl < 2; mtl++)                                 \
                ldsm4(ah[ks][mtl][0], ah[ks][mtl][1], ah[ks][mtl][2],         \
                      ah[ks][mtl][3], aLin + (uint32_t)(mtl * 4096) + ko);    \
        }                                                                     \
    }
    // flush: quad-lane reduce -> red -> g_part[idx]; resets s
#define FLUSH(IDX)                                                            \
    {                                                                         \
        _Pragma("unroll")                                                     \
        for (int k = 0; k < 4; k++) {                                         \
            s[k] += __shfl_xor_sync(0xffffffffu, s[k], 1);                    \
            s[k] += __shfl_xor_sync(0xffffffffu, s[k], 2);                    \
        }                                                                     \
        __syncthreads();                                                      \
        if ((lane & 3) == 0) {                                                \
            _Pragma("unroll")                                                 \
            for (int mtl = 0; mtl < 2; mtl++)                                 \
                _Pragma("unroll")                                             \
                for (int h = 0; h < 2; h++) {                                 \
                    int row = wm * 32 + mtl * 16 + h * 8 + (lane >> 2);       \
                    red[row * 2 + wn] = s[mtl * 2 + h];                       \
                }                                                             \
        }                                                                     \
        __syncthreads();                                                      \
        if (tid < 128) g_part[(IDX) * 128 + tid] = red[tid * 2] + red[tid * 2 + 1]; \
        s[0] = s[1] = s[2] = s[3] = 0.f;                                      \
    }

    mbar_wait(sb + MB_X, xph); xph ^= 1;
    LOAD_A();
    __syncthreads();                 // all warps done reading OFF_X
    if (twoseg && tid == 0) {        // prefetch next mtile's x panel now
        mbar_expect(sb + MB_X, 32768);
        bulk_g2s(sb + OFF_X, g_x + (size_t)mt1 * 32768, 32768, sb + MB_X);
    }
    LOAD_AX(mt0);

    for (int j = 0; j < J; j++) {
        if (twoseg && j == len0) {   // segment boundary: flush + switch mtile
            FLUSH(cta * 2);
            mbar_wait(sb + MB_X, xph); xph ^= 1;
            LOAD_A();
            LOAD_AX(mt1);
        }
        const int st = j & (NSTAGE - 1);
        mbar_wait(sb + MB_S + st * 8, (phmask >> st) & 1);
        phmask ^= 1u << st;

        float acc[64];
        const uint32_t pb = sb + OFF_M + st * 32768 + bLin;
#pragma unroll
        for (int ks = 0; ks < 8; ks++) {
            const uint32_t ko = ((uint32_t)(ks * 32) + h16) ^ sx;
            uint32_t bf[4][4];
#pragma unroll
            for (int np = 0; np < 4; np++)
                ldsm4(bf[np][0], bf[np][1], bf[np][2], bf[np][3], pb + np * 4096 + ko);
#pragma unroll
            for (int mtl = 0; mtl < 2; mtl++)
#pragma unroll
                for (int np = 0; np < 4; np++) {
                    float* cc0 = &acc[(mtl * 8 + np * 2) * 4];
                    float* cc1 = &acc[(mtl * 8 + np * 2 + 1) * 4];
                    if (ks == 0) {
                        mma16816_z(cc0[0], cc0[1], cc0[2], cc0[3],
                                   ah[ks][mtl][0], ah[ks][mtl][1],
                                   ah[ks][mtl][2], ah[ks][mtl][3],
                                   bf[np][0], bf[np][2]);
                        mma16816_z(cc1[0], cc1[1], cc1[2], cc1[3],
                                   ah[ks][mtl][0], ah[ks][mtl][1],
                                   ah[ks][mtl][2], ah[ks][mtl][3],
                                   bf[np][1], bf[np][3]);
                    } else {
                        mma16816(cc0[0], cc0[1], cc0[2], cc0[3],
                                 ah[ks][mtl][0], ah[ks][mtl][1],
                                 ah[ks][mtl][2], ah[ks][mtl][3],
                                 bf[np][0], bf[np][2]);
                        mma16816(cc1[0], cc1[1], cc1[2], cc1[3],
                                 ah[ks][mtl][0], ah[ks][mtl][1],
                                 ah[ks][mtl][2], ah[ks][mtl][3],
                                 bf[np][1], bf[np][3]);
                    }
                }
        }

        // fused epilogue (bw slot st still valid; refill comes after the sync)
        const float4* bwp = reinterpret_cast<const float4*>(smem + OFF_BW + st * 1024);
#pragma unroll
        for (int nt = 0; nt < 8; nt++) {
            float4 bw4 = bwp[bwIdx + nt * 4];
#pragma unroll
            for (int mtl = 0; mtl < 2; mtl++)
#pragma unroll
                for (int h = 0; h < 2; h++) {
                    float d0 = acc[(mtl * 8 + nt) * 4 + h * 2];
                    float d1 = acc[(mtl * 8 + nt) * 4 + h * 2 + 1];
                    float base = axv[mtl * 2 + h];
                    float e0 = ex2_pred(fmaf(LOG2E_F, d0, base + bw4.x));
                    float e1 = ex2_pred(fmaf(LOG2E_F, d1, base + bw4.z));
                    s[mtl * 2 + h] = fmaf(bw4.y, e0, s[mtl * 2 + h]);
                    s[mtl * 2 + h] = fmaf(bw4.w, e1, s[mtl * 2 + h]);
                }
        }

        __syncthreads();             // stage st fully consumed by all warps
        if (tid == 0 && j + NSTAGE < J) {
            const int cn = CHUNK(j + NSTAGE);
            const uint32_t mb = sb + MB_S + st * 8;
            mbar_expect(mb, 33792);
            bulk_g2s(sb + OFF_M + st * 32768, g_m + (size_t)cn * 32768, 32768, mb);
            bulk_g2s(sb + OFF_BW + st * 1024, (const char*)g_bw + (size_t)cn * 1024, 1024, mb);
        }
    }

    FLUSH(cta * 2 + (twoseg ? 1 : 0));
}

// ---------------- reduce: recombine per-CTA partials -> out ----------------
__global__ void reduce_out(float* __restrict__ out) {
    const int mt = blockIdx.x;         // 128 mtiles
    const int r = threadIdx.x;         // 128 rows
    const uint32_t mtStart = (uint32_t)mt * 64, mtEnd = mtStart + 64;
    const int w = (mt * 37) >> 5;      // ~ mt*NCTA/128
    float sum = 0.f;
    const int clo = w - 2 < 0 ? 0 : w - 2;
    const int chi = w + 3 > NCTA - 1 ? NCTA - 1 : w + 3;
    for (int c = clo; c <= chi; c++) {
        uint32_t s0 = (uint32_t)(c * NTASK) / NCTA;
        uint32_t e0 = (uint32_t)((c + 1) * NTASK) / NCTA;
        if (s0 < mtEnd && e0 > mtStart) {
            int seg = ((int)(s0 >> 6) == mt) ? 0 : 1;
            sum += g_part[(c * 2 + seg) * 128 + r];
        }
    }
    out[mt * 128 + r] = sum;
}

// ---------------------------------------------------------------------------
extern "C" void kernel_launch(void* const* d_in, const int* in_sizes, int n_in,
                              void* d_out, int out_size) {
    const float* x = (const float*)d_in[0];      // [16384, 128]
    const float* means = (const float*)d_in[1];  // [8192, 128]
    const float* w = (const float*)d_in[2];      // [8192]
    float* out = (float*)d_out;                  // [16384]
    (void)in_sizes; (void)n_in; (void)out_size;

    cudaFuncSetAttribute(gmm_mma, cudaFuncAttributeMaxDynamicSharedMemorySize, SMEM_BYTES);

    prep<<<(M_DIM + N_DIM) / 8, 256>>>(x, means, w);
    gmm_mma<<<NCTA, 256, SMEM_BYTES>>>();
    reduce_out<<<128, 128>>>(out);
}